// round 4
// baseline (speedup 1.0000x reference)
#include <cuda_runtime.h>
#include <cuda_bf16.h>

#define BATCH 8
#define CDIM 256
#define CQK 32
#define NPIX 16384
#define TILE_N 128
#define XS_STRIDE 132

// ---------------- scratch (device globals; no allocation allowed) ----------------
__device__ float g_Qn[BATCH * CQK * NPIX];     // normalized Q, [b][m][n]
__device__ float g_S[BATCH * CQK * CDIM];      // S = Kn @ X^T
__device__ float g_ksum[BATCH * CQK];          // sum_n Kn
__device__ float g_xsum[BATCH * CDIM];         // sum_n X
__device__ float g_matrix[BATCH * CQK * CDIM]; // Kn @ V^T (derived)
__device__ float g_vs[BATCH * CDIM];           // value_sum
__device__ float g_kse[BATCH * CQK];           // ksum + EPS

// ---------------- init: zero the accumulated scratch ----------------
__global__ void kinit_kernel() {
    int i = blockIdx.x * blockDim.x + threadIdx.x;
    int stride = gridDim.x * blockDim.x;
    for (int t = i; t < BATCH * CQK * CDIM; t += stride) g_S[t] = 0.f;
    for (int t = i; t < BATCH * CQK; t += stride) g_ksum[t] = 0.f;
    for (int t = i; t < BATCH * CDIM; t += stride) g_xsum[t] = 0.f;
}

// ---------------- kernel 1: Q/K GEMM + normalize + ksum/xsum + S GEMM ----------------
// grid (NPIX/TILE_N, BATCH), 512 threads, dynamic smem.
// smem layout (floats):
//   Xs   [256][132]   X tile (padded stride)
//   KtT  [128][32]    normalized K, transposed, XOR-swizzled columns
//   Ws   [64][32]     staged W chunk ([Wq;Wk] rows x 32 c)
//   qn2[128], kn2[128], ksum_s[32]
#define K1_SMEM_FLOATS (256 * XS_STRIDE + 128 * 32 + 64 * 32 + 128 + 128 + 32)

__global__ __launch_bounds__(512, 1) void k1_kernel(
    const float* __restrict__ x,
    const float* __restrict__ Wq, const float* __restrict__ bq,
    const float* __restrict__ Wk, const float* __restrict__ bk)
{
    extern __shared__ float sm[];
    float* Xs  = sm;
    float* KtT = Xs + 256 * XS_STRIDE;
    float* Ws  = KtT + 128 * 32;
    float* qn2 = Ws + 64 * 32;
    float* kn2 = qn2 + 128;
    float* ksum_s = kn2 + 128;

    const int b   = blockIdx.y;
    const int n0  = blockIdx.x * TILE_N;
    const int tid = threadIdx.x;

    // --- load X tile [256 x 128] (each warp loads one full 512B row) ---
    const float* xb = x + (size_t)b * CDIM * NPIX;
    #pragma unroll
    for (int i = 0; i < 16; i++) {
        int f4 = tid + 512 * i;
        int c  = f4 >> 5;
        int j4 = (f4 & 31) << 2;
        float4 v = *(const float4*)(xb + (size_t)c * NPIX + n0 + j4);
        *(float4*)(Xs + c * XS_STRIDE + j4) = v;
    }
    if (tid < 128) { qn2[tid] = 0.f; kn2[tid] = 0.f; }
    else if (tid < 160) ksum_s[tid - 128] = 0.f;
    __syncthreads();

    // --- QK GEMM: rows 0..31 = Q, 32..63 = K; 4 rows x 4 cols per thread ---
    const int jc  = tid & 31;
    const int jc4 = jc << 2;
    const int r0  = (tid >> 5) << 2;   // 0..60
    float acc[4][4] = {};

    for (int cc = 0; cc < 256; cc += 32) {
        {   // stage W chunk [64][32]
            int r  = tid >> 3;
            int k4 = (tid & 7) << 2;
            const float* src = (r < 32) ? (Wq + r * 256 + cc + k4)
                                        : (Wk + (r - 32) * 256 + cc + k4);
            *(float4*)(Ws + r * 32 + k4) = *(const float4*)src;
        }
        __syncthreads();
        #pragma unroll
        for (int k = 0; k < 32; k += 4) {
            float xv[4][4];
            #pragma unroll
            for (int kk = 0; kk < 4; kk++) {
                float4 t4 = *(const float4*)(Xs + (cc + k + kk) * XS_STRIDE + jc4);
                xv[kk][0] = t4.x; xv[kk][1] = t4.y; xv[kk][2] = t4.z; xv[kk][3] = t4.w;
            }
            #pragma unroll
            for (int rr = 0; rr < 4; rr++) {
                float4 w4 = *(const float4*)(Ws + (r0 + rr) * 32 + k);
                float wf[4] = {w4.x, w4.y, w4.z, w4.w};
                #pragma unroll
                for (int kk = 0; kk < 4; kk++)
                    #pragma unroll
                    for (int cl = 0; cl < 4; cl++)
                        acc[rr][cl] = fmaf(wf[kk], xv[kk][cl], acc[rr][cl]);
            }
        }
        __syncthreads();
    }

    // --- bias ---
    const bool isQ = (r0 < 32);
    #pragma unroll
    for (int rr = 0; rr < 4; rr++) {
        int r = r0 + rr;
        float bias = isQ ? bq[r] : bk[r - 32];
        #pragma unroll
        for (int cl = 0; cl < 4; cl++) acc[rr][cl] += bias;
    }

    // --- xsum partial (independent of norms) ---
    {
        int c  = tid >> 1;
        int h0 = (tid & 1) << 6;
        float s = 0.f;
        #pragma unroll 8
        for (int i = 0; i < 64; i++) {
            int j = h0 + ((i + (tid & 31)) & 63);
            s += Xs[c * XS_STRIDE + j];
        }
        atomicAdd(&g_xsum[b * CDIM + c], s);
    }

    // --- per-column sum of squares ---
    {
        float* n2 = isQ ? qn2 : kn2;
        #pragma unroll
        for (int cl = 0; cl < 4; cl++) {
            float ss = acc[0][cl] * acc[0][cl] + acc[1][cl] * acc[1][cl]
                     + acc[2][cl] * acc[2][cl] + acc[3][cl] * acc[3][cl];
            atomicAdd(&n2[jc4 + cl], ss);
        }
    }
    __syncthreads();

    // --- normalize: Q -> global, K -> smem (transposed + swizzled) + ksum ---
    if (isQ) {
        float rn[4];
        #pragma unroll
        for (int cl = 0; cl < 4; cl++) rn[cl] = rsqrtf(qn2[jc4 + cl]);
        #pragma unroll
        for (int rr = 0; rr < 4; rr++) {
            float4 o;
            o.x = acc[rr][0] * rn[0]; o.y = acc[rr][1] * rn[1];
            o.z = acc[rr][2] * rn[2]; o.w = acc[rr][3] * rn[3];
            *(float4*)(g_Qn + (size_t)(b * CQK + r0 + rr) * NPIX + n0 + jc4) = o;
        }
    } else {
        float rn[4];
        #pragma unroll
        for (int cl = 0; cl < 4; cl++) rn[cl] = rsqrtf(kn2[jc4 + cl]);
        const int sw = (tid & 7) << 2;   // = ((j>>2)&7)<<2 for this thread's cols
        #pragma unroll
        for (int rr = 0; rr < 4; rr++) {
            int m  = r0 - 32 + rr;
            int mp = m ^ sw;
            float ks = 0.f;
            #pragma unroll
            for (int cl = 0; cl < 4; cl++) {
                float v = acc[rr][cl] * rn[cl];
                KtT[(jc4 + cl) * 32 + mp] = v;
                ks += v;
            }
            atomicAdd(&ksum_s[m], ks);
        }
    }
    __syncthreads();

    if (tid < 32) atomicAdd(&g_ksum[b * CQK + tid], ksum_s[tid]);

    // --- S GEMM: S[m][c] += sum_j Kn[m][j] * X[c][j]; 4m x 4c per thread ---
    const int m0s = (tid & 7) << 2;
    const int cg  = tid >> 3;          // 0..63; c = cg + 64*ci
    float sacc[4][4] = {};
    #pragma unroll 4
    for (int j = 0; j < 128; j += 4) {
        const int sw = ((j >> 2) & 7) << 2;
        float kv[4][4];
        #pragma unroll
        for (int jj = 0; jj < 4; jj++) {
            float4 k4 = *(const float4*)(KtT + (j + jj) * 32 + (m0s ^ sw));
            kv[jj][0] = k4.x; kv[jj][1] = k4.y; kv[jj][2] = k4.z; kv[jj][3] = k4.w;
        }
        float xr[4][4];
        #pragma unroll
        for (int ci = 0; ci < 4; ci++) {
            float4 x4 = *(const float4*)(Xs + (cg + (ci << 6)) * XS_STRIDE + j);
            xr[ci][0] = x4.x; xr[ci][1] = x4.y; xr[ci][2] = x4.z; xr[ci][3] = x4.w;
        }
        #pragma unroll
        for (int mi = 0; mi < 4; mi++)
            #pragma unroll
            for (int ci = 0; ci < 4; ci++) {
                sacc[mi][ci] = fmaf(kv[0][mi], xr[ci][0], sacc[mi][ci]);
                sacc[mi][ci] = fmaf(kv[1][mi], xr[ci][1], sacc[mi][ci]);
                sacc[mi][ci] = fmaf(kv[2][mi], xr[ci][2], sacc[mi][ci]);
                sacc[mi][ci] = fmaf(kv[3][mi], xr[ci][3], sacc[mi][ci]);
            }
    }
    #pragma unroll
    for (int mi = 0; mi < 4; mi++)
        #pragma unroll
        for (int ci = 0; ci < 4; ci++)
            atomicAdd(&g_S[(b * CQK + m0s + mi) * CDIM + cg + (ci << 6)], sacc[mi][ci]);
}

// ---------------- kernel 2: matrix = S @ Wv^T + ksum (x) bv ; value_sum ----------------
// grid (33, BATCH), 256 threads. Block m<32 -> matrix row m; block 32 -> value_sum.
__global__ __launch_bounds__(256) void k2_kernel(
    const float* __restrict__ Wv, const float* __restrict__ bv)
{
    __shared__ float Wvs[256 * 33];
    __shared__ float Ss[256];
    const int b   = blockIdx.y;
    const int m   = blockIdx.x;
    const int tid = threadIdx.x;

    const float* srow = (m < 32) ? (g_S + (b * CQK + m) * CDIM) : (g_xsum + b * CDIM);
    Ss[tid] = srow[tid];

    float acc = 0.f;
    for (int k0 = 0; k0 < 256; k0 += 32) {
        #pragma unroll
        for (int i = 0; i < 8; i++) {
            int f4 = tid + 256 * i;
            int r  = f4 >> 3;
            int k4 = (f4 & 7) << 2;
            float4 w = *(const float4*)(Wv + r * 256 + k0 + k4);
            float* d = Wvs + r * 33 + k4;
            d[0] = w.x; d[1] = w.y; d[2] = w.z; d[3] = w.w;
        }
        __syncthreads();
        #pragma unroll
        for (int kk = 0; kk < 32; kk++)
            acc = fmaf(Wvs[tid * 33 + kk], Ss[k0 + kk], acc);
        __syncthreads();
    }

    if (m < 32) {
        float bm = g_ksum[b * CQK + m];
        g_matrix[(b * CQK + m) * CDIM + tid] = acc + bv[tid] * bm;
    } else {
        g_vs[b * CDIM + tid] = acc + 16384.0f * bv[tid];
        if (tid < 32) g_kse[b * CQK + tid] = g_ksum[b * CQK + tid] + 1e-6f;
    }
}

// ---------------- kernel 3: out = x + gamma * tailor * (vs + matrix^T @ q) ----------------
// grid (NPIX/128, BATCH), 128 threads, one pixel column per thread.
__global__ __launch_bounds__(128, 8) void k3_kernel(
    const float* __restrict__ x, const float* __restrict__ gamma,
    float* __restrict__ out)
{
    __shared__ float Ms[CQK * CDIM];
    __shared__ float vs_s[CDIM];
    __shared__ float ks_s[CQK];

    const int b   = blockIdx.y;
    const int tid = threadIdx.x;
    const int n   = blockIdx.x * 128 + tid;

    const float* mb = g_matrix + b * CQK * CDIM;
    #pragma unroll
    for (int i = 0; i < 16; i++) {
        int f4 = tid + 128 * i;
        *(float4*)(Ms + f4 * 4) = *(const float4*)(mb + f4 * 4);
    }
    vs_s[tid]       = g_vs[b * CDIM + tid];
    vs_s[tid + 128] = g_vs[b * CDIM + tid + 128];
    if (tid < 32) ks_s[tid] = g_kse[b * CQK + tid];
    __syncthreads();

    float q[32];
    const float* qp = g_Qn + (size_t)b * CQK * NPIX + n;
    #pragma unroll
    for (int m = 0; m < 32; m++) q[m] = qp[m * NPIX];

    float denom = 16384.0f;
    #pragma unroll
    for (int m = 0; m < 32; m++) denom += q[m] * ks_s[m];
    const float gt = gamma[0] / denom;   // gamma * tailor

    const float* xb = x   + (size_t)b * CDIM * NPIX + n;
    float*       ob = out + (size_t)b * CDIM * NPIX + n;

    #pragma unroll 2
    for (int c4 = 0; c4 < 256; c4 += 4) {
        float u0 = vs_s[c4], u1 = vs_s[c4 + 1], u2 = vs_s[c4 + 2], u3 = vs_s[c4 + 3];
        #pragma unroll
        for (int m = 0; m < 32; m++) {
            float4 m4 = *(const float4*)(Ms + m * 256 + c4);
            float qm = q[m];
            u0 = fmaf(qm, m4.x, u0);
            u1 = fmaf(qm, m4.y, u1);
            u2 = fmaf(qm, m4.z, u2);
            u3 = fmaf(qm, m4.w, u3);
        }
        int off = c4 * NPIX;
        ob[off]             = xb[off]             + gt * u0;
        ob[off + NPIX]      = xb[off + NPIX]      + gt * u1;
        ob[off + 2 * NPIX]  = xb[off + 2 * NPIX]  + gt * u2;
        ob[off + 3 * NPIX]  = xb[off + 3 * NPIX]  + gt * u3;
    }
}

// ---------------- launch ----------------
extern "C" void kernel_launch(void* const* d_in, const int* in_sizes, int n_in,
                              void* d_out, int out_size)
{
    (void)in_sizes; (void)n_in; (void)out_size;
    const float* x     = (const float*)d_in[0];
    const float* Wq    = (const float*)d_in[1];
    const float* bq    = (const float*)d_in[2];
    const float* Wk    = (const float*)d_in[3];
    const float* bk    = (const float*)d_in[4];
    const float* Wv    = (const float*)d_in[5];
    const float* bv    = (const float*)d_in[6];
    const float* gamma = (const float*)d_in[7];
    float* out = (float*)d_out;

    const int k1_smem = K1_SMEM_FLOATS * (int)sizeof(float);  // ~157 KB
    cudaFuncSetAttribute(k1_kernel, cudaFuncAttributeMaxDynamicSharedMemorySize, k1_smem);

    kinit_kernel<<<64, 256>>>();
    k1_kernel<<<dim3(NPIX / TILE_N, BATCH), 512, k1_smem>>>(x, Wq, bq, Wk, bk);
    k2_kernel<<<dim3(33, BATCH), 256>>>(Wv, bv);
    k3_kernel<<<dim3(NPIX / 128, BATCH), 128>>>(x, gamma, out);
}

// round 8
// speedup vs baseline: 2.2851x; 2.2851x over previous
#include <cuda_runtime.h>
#include <cuda_bf16.h>
#include <cstdint>

#define BATCH 8
#define CDIM 256
#define CQK 32
#define NPIX 16384
#define TILE_N 128

// ---------------- device-global scratch ----------------
__device__ float    g_S[BATCH * CQK * CDIM];       // S = Kn @ X^T (fp32 atomic accum)
__device__ float    g_ksum[BATCH * CQK];
__device__ float    g_xsum[BATCH * CDIM];
__device__ float    g_vs[BATCH * CDIM];
__device__ float    g_kse[BATCH * CQK];
__device__ uint32_t g_Qnh2[BATCH * 16 * NPIX];     // Qn bf162 m-pairs: [b][m2][n]
__device__ uint32_t g_Wt2[128 * 64];               // [Wq;Wk] bf162 c-pairs: [c2][r]
__device__ __nv_bfloat16 g_matTh[BATCH * CDIM * CQK]; // matrix^T bf16: [b][c][m]

// ---------------- helpers ----------------
__device__ __forceinline__ uint32_t packbf(float lo, float hi) {
    __nv_bfloat162 h = __float22bfloat162_rn(make_float2(lo, hi));
    return *reinterpret_cast<uint32_t*>(&h);
}

__device__ __forceinline__ void mma16816(float* d,
    uint32_t a0, uint32_t a1, uint32_t a2, uint32_t a3,
    uint32_t b0, uint32_t b1)
{
    asm volatile(
        "mma.sync.aligned.m16n8k16.row.col.f32.bf16.bf16.f32 "
        "{%0,%1,%2,%3}, {%4,%5,%6,%7}, {%8,%9}, {%0,%1,%2,%3};"
        : "+f"(d[0]), "+f"(d[1]), "+f"(d[2]), "+f"(d[3])
        : "r"(a0), "r"(a1), "r"(a2), "r"(a3), "r"(b0), "r"(b1));
}

// ---------------- kinit: zero accumulators + build bf16 Wqk (c-pair interleaved) ----------------
__global__ void kinit_kernel(const float* __restrict__ Wq, const float* __restrict__ Wk) {
    int i = blockIdx.x * blockDim.x + threadIdx.x;
    int st = gridDim.x * blockDim.x;
    for (int t = i; t < BATCH * CQK * CDIM; t += st) g_S[t] = 0.f;
    for (int t = i; t < BATCH * CQK;  t += st) g_ksum[t] = 0.f;
    for (int t = i; t < BATCH * CDIM; t += st) g_xsum[t] = 0.f;
    for (int t = i; t < 128 * 64; t += st) {
        int c2 = t >> 6, r = t & 63;
        const float* Wr = (r < 32) ? (Wq + r * 256) : (Wk + (r - 32) * 256);
        g_Wt2[t] = packbf(Wr[2 * c2], Wr[2 * c2 + 1]);
    }
}

// ---------------- kernel 1: QK mma + normalize + ksum/xsum + S mma ----------------
// grid (128, 8), 256 threads, dynamic smem 185216 B.
// smem (uint32 words):
//   Xh2  [c2=128][n=128] stride 136  (bf162 c-pairs)      17408 w
//   Xrow [c=256][n2=64]  stride 68   (bf162 n-pairs)      17408 w
//   Wt2  [c2=128][r=64]  stride 72                         9216 w
//   Kns  [m=32][n2=64]   stride 68   (bf16, n-contig)      2176 w
//   bias[64], ksum_s[32]
#define K1_XH2   0
#define K1_XROW  17408
#define K1_WT2   34816
#define K1_KNS   44032
#define K1_BIAS  46208
#define K1_KSUM  46272
#define K1_WORDS 46304

__global__ __launch_bounds__(256, 1) void k1_kernel(
    const float* __restrict__ x,
    const float* __restrict__ bq, const float* __restrict__ bk)
{
    extern __shared__ uint32_t sw[];
    uint32_t* Xh2  = sw + K1_XH2;
    uint32_t* Xrow = sw + K1_XROW;
    uint32_t* Wt2  = sw + K1_WT2;
    uint32_t* KnsW = sw + K1_KNS;
    float* bias_s  = (float*)(sw + K1_BIAS);
    float* ksum_s  = (float*)(sw + K1_KSUM);
    __nv_bfloat16* KnsH = (__nv_bfloat16*)KnsW;

    const int b   = blockIdx.y;
    const int n0  = blockIdx.x * TILE_N;
    const int tid = threadIdx.x;
    const int w    = tid >> 5;
    const int lane = tid & 31;
    const int g    = lane >> 2;    // 0..7
    const int tg   = lane & 3;     // 0..3

    // stage Wt2 (global [c2][r] stride 64 -> smem stride 72)
    {
        int c2 = tid >> 1, hb = (tid & 1) * 32;
        const uint32_t* src = g_Wt2 + c2 * 64 + hb;
        uint32_t* dst = Wt2 + c2 * 72 + hb;
        #pragma unroll
        for (int j = 0; j < 32; j += 4) *(uint4*)(dst + j) = *(const uint4*)(src + j);
    }
    if (tid < 64) bias_s[tid] = (tid < 32) ? bq[tid] : bk[tid - 32];
    if (tid < 32) ksum_s[tid] = 0.f;

    // --- load X tile: warp w owns rows c = 32w..32w+31 (coalesced 512B rows) ---
    const float* xb = x + (size_t)b * CDIM * NPIX + n0;
    {
        float4 prev = make_float4(0.f, 0.f, 0.f, 0.f);
        #pragma unroll 4
        for (int i = 0; i < 32; i++) {
            int c = 32 * w + i;
            float4 v = *(const float4*)(xb + (size_t)c * NPIX + 4 * lane);
            uint2 rw;
            rw.x = packbf(v.x, v.y); rw.y = packbf(v.z, v.w);
            *(uint2*)(Xrow + c * 68 + 2 * lane) = rw;
            if (i & 1) {
                uint4 hw;
                hw.x = packbf(prev.x, v.x); hw.y = packbf(prev.y, v.y);
                hw.z = packbf(prev.z, v.z); hw.w = packbf(prev.w, v.w);
                *(uint4*)(Xh2 + (c >> 1) * 136 + 4 * lane) = hw;
            } else prev = v;
        }
    }
    __syncthreads();

    // --- xsum from bf16 Xrow (consistent with bf16 GEMM path) ---
    {
        float s = 0.f;
        const uint32_t* row = Xrow + tid * 68;
        #pragma unroll 8
        for (int j = 0; j < 64; j++) {
            float2 f = __bfloat1622float2(*(const __nv_bfloat162*)&row[j]);
            s += f.x + f.y;
        }
        atomicAdd(&g_xsum[b * CDIM + tid], s);
    }

    // --- QK GEMM (mma): out[n][r], M=128(n) N=64(r) K=256(c); warp = n-slice 16 ---
    float acc[8][4];
    #pragma unroll
    for (int t = 0; t < 8; t++) { acc[t][0] = acc[t][1] = acc[t][2] = acc[t][3] = 0.f; }
    const int nbase = 16 * w;

    for (int ks = 0; ks < 16; ks++) {
        const uint32_t* Ap = Xh2 + (8 * ks + tg) * 136 + nbase + g;
        uint32_t a0 = Ap[0], a1 = Ap[8], a2 = Ap[4 * 136], a3 = Ap[4 * 136 + 8];
        const uint32_t* Bp = Wt2 + (8 * ks + tg) * 72 + g;
        #pragma unroll
        for (int t = 0; t < 8; t++)
            mma16816(acc[t], a0, a1, a2, a3, Bp[8 * t], Bp[4 * 72 + 8 * t]);
    }

    // --- bias + per-pixel channel norms (Q: tiles 0..3 = r 0..31, K: tiles 4..7) ---
    float qn2a = 0.f, qn2b = 0.f, kn2a = 0.f, kn2b = 0.f;
    #pragma unroll
    for (int t = 0; t < 8; t++) {
        float b0 = bias_s[8 * t + 2 * tg], b1 = bias_s[8 * t + 2 * tg + 1];
        acc[t][0] += b0; acc[t][1] += b1; acc[t][2] += b0; acc[t][3] += b1;
        if (t < 4) {
            qn2a += acc[t][0] * acc[t][0] + acc[t][1] * acc[t][1];
            qn2b += acc[t][2] * acc[t][2] + acc[t][3] * acc[t][3];
        } else {
            kn2a += acc[t][0] * acc[t][0] + acc[t][1] * acc[t][1];
            kn2b += acc[t][2] * acc[t][2] + acc[t][3] * acc[t][3];
        }
    }
    // reduce over the 4 lanes sharing the same n (same g, tg=0..3 hold disjoint r)
    qn2a += __shfl_xor_sync(0xffffffffu, qn2a, 1); qn2a += __shfl_xor_sync(0xffffffffu, qn2a, 2);
    qn2b += __shfl_xor_sync(0xffffffffu, qn2b, 1); qn2b += __shfl_xor_sync(0xffffffffu, qn2b, 2);
    kn2a += __shfl_xor_sync(0xffffffffu, kn2a, 1); kn2a += __shfl_xor_sync(0xffffffffu, kn2a, 2);
    kn2b += __shfl_xor_sync(0xffffffffu, kn2b, 1); kn2b += __shfl_xor_sync(0xffffffffu, kn2b, 2);
    const float rqa = rsqrtf(qn2a), rqb = rsqrtf(qn2b);
    const float rka = rsqrtf(kn2a), rkb = rsqrtf(kn2b);

    // --- Qn -> global bf162 m-pairs [b][m2][n] ---
    {
        uint32_t* qdst = g_Qnh2 + (size_t)b * 16 * NPIX + n0 + nbase + g;
        #pragma unroll
        for (int t = 0; t < 4; t++) {
            int r2 = 4 * t + tg;
            qdst[(size_t)r2 * NPIX]     = packbf(acc[t][0] * rqa, acc[t][1] * rqa);
            qdst[(size_t)r2 * NPIX + 8] = packbf(acc[t][2] * rqb, acc[t][3] * rqb);
        }
    }

    // --- Kn -> smem bf16 [m][n] (n-contiguous for S-GEMM B... used as A) ---
    #pragma unroll
    for (int t = 4; t < 8; t++) {
        int m = 8 * (t - 4) + 2 * tg;
        int nn = nbase + g;
        KnsH[m * 136 + nn]           = __float2bfloat16(acc[t][0] * rka);
        KnsH[(m + 1) * 136 + nn]     = __float2bfloat16(acc[t][1] * rka);
        KnsH[m * 136 + nn + 8]       = __float2bfloat16(acc[t][2] * rkb);
        KnsH[(m + 1) * 136 + nn + 8] = __float2bfloat16(acc[t][3] * rkb);
    }
    __syncthreads();

    // --- ksum ---
    {
        int m = tid >> 3, j0 = (tid & 7) * 16;
        float s = 0.f;
        #pragma unroll
        for (int j = 0; j < 16; j++) s += __bfloat162float(KnsH[m * 136 + j0 + j]);
        atomicAdd(&ksum_s[m], s);
    }
    __syncthreads();
    if (tid < 32) atomicAdd(&g_ksum[b * CQK + tid], ksum_s[tid]);

    // --- S GEMM (mma): S[m][c] += Kn @ X^T; M=32 N=256 K=128; warp = (m16) x (c64) ---
    float sa[8][4];
    #pragma unroll
    for (int t = 0; t < 8; t++) { sa[t][0] = sa[t][1] = sa[t][2] = sa[t][3] = 0.f; }
    const int m0 = 16 * (w & 1), c0 = 64 * (w >> 1);

    #pragma unroll
    for (int ks = 0; ks < 8; ks++) {
        const uint32_t* Ap = KnsW + (m0 + g) * 68 + 8 * ks + tg;
        uint32_t a0 = Ap[0], a1 = Ap[8 * 68], a2 = Ap[4], a3 = Ap[8 * 68 + 4];
        const uint32_t* Bp = Xrow + (c0 + g) * 68 + 8 * ks + tg;
        #pragma unroll
        for (int t = 0; t < 8; t++)
            mma16816(sa[t], a0, a1, a2, a3, Bp[8 * t * 68], Bp[8 * t * 68 + 4]);
    }
    float* Sb = g_S + (size_t)b * CQK * CDIM;
    #pragma unroll
    for (int t = 0; t < 8; t++) {
        int c = c0 + 8 * t + 2 * tg;
        atomicAdd(&Sb[(m0 + g) * CDIM + c],       sa[t][0]);
        atomicAdd(&Sb[(m0 + g) * CDIM + c + 1],   sa[t][1]);
        atomicAdd(&Sb[(m0 + g + 8) * CDIM + c],   sa[t][2]);
        atomicAdd(&Sb[(m0 + g + 8) * CDIM + c + 1], sa[t][3]);
    }
}

// ---------------- kernel 2: matrix^T (bf16) = (S @ Wv^T + ksum x bv)^T ; value_sum ----------------
__global__ __launch_bounds__(256) void k2_kernel(
    const float* __restrict__ Wv, const float* __restrict__ bv)
{
    __shared__ float Wvs[256 * 33];
    __shared__ float Ss[256];
    const int b   = blockIdx.y;
    const int m   = blockIdx.x;
    const int tid = threadIdx.x;

    const float* srow = (m < 32) ? (g_S + (b * CQK + m) * CDIM) : (g_xsum + b * CDIM);
    Ss[tid] = srow[tid];

    float acc = 0.f;
    for (int k0 = 0; k0 < 256; k0 += 32) {
        #pragma unroll
        for (int i = 0; i < 8; i++) {
            int f4 = tid + 256 * i;
            int r  = f4 >> 3;
            int k4 = (f4 & 7) << 2;
            float4 wv = *(const float4*)(Wv + r * 256 + k0 + k4);
            float* d = Wvs + r * 33 + k4;
            d[0] = wv.x; d[1] = wv.y; d[2] = wv.z; d[3] = wv.w;
        }
        __syncthreads();
        #pragma unroll
        for (int kk = 0; kk < 32; kk++)
            acc = fmaf(Wvs[tid * 33 + kk], Ss[k0 + kk], acc);
        __syncthreads();
    }

    if (m < 32) {
        float bm = g_ksum[b * CQK + m];
        g_matTh[((size_t)b * CDIM + tid) * CQK + m] = __float2bfloat16(acc + bv[tid] * bm);
    } else {
        g_vs[b * CDIM + tid] = acc + 16384.0f * bv[tid];
        if (tid < 32) g_kse[b * CQK + tid] = g_ksum[b * CQK + tid] + 1e-6f;
    }
}

// ---------------- kernel 3 (mma): out = x + gt * (vs + matrix^T @ Qn) ----------------
// grid (64, 8), 256 threads. Tile: 256 channels x 256 pixels.
__global__ __launch_bounds__(256, 2) void k3_kernel(
    const float* __restrict__ x, const float* __restrict__ gamma,
    float* __restrict__ out)
{
    __shared__ uint32_t matTs[256 * 20];   // A: [c][m2] stride 20
    __shared__ uint32_t Qns[16 * 264];     // B: [m2][n] stride 264
    __shared__ float gt_s[256];
    __shared__ float vs_s[256];
    __shared__ float kse_s[32];

    const int b    = blockIdx.y;
    const int nb0  = blockIdx.x * 256;
    const int tid  = threadIdx.x;
    const int w    = tid >> 5;
    const int lane = tid & 31;
    const int g    = lane >> 2;
    const int tg   = lane & 3;

    // stage matrix^T (bf162 m-pairs) and Qn tile
    {
        const uint32_t* mt = (const uint32_t*)g_matTh + ((size_t)b * CDIM + tid) * 16;
        uint32_t* dst = matTs + tid * 20;
        #pragma unroll
        for (int j = 0; j < 16; j += 4) *(uint4*)(dst + j) = *(const uint4*)(mt + j);
    }
    #pragma unroll
    for (int i = 0; i < 16; i++)
        Qns[i * 264 + tid] = g_Qnh2[((size_t)b * 16 + i) * NPIX + nb0 + tid];
    vs_s[tid] = g_vs[b * CDIM + tid];
    if (tid < 32) kse_s[tid] = g_kse[b * CQK + tid];
    __syncthreads();

    // gt[n] = gamma / (N + sum_m q[m]*kse[m])
    {
        float den = 16384.0f;
        #pragma unroll
        for (int m2 = 0; m2 < 16; m2++) {
            float2 q2 = __bfloat1622float2(*(const __nv_bfloat162*)&Qns[m2 * 264 + tid]);
            den += q2.x * kse_s[2 * m2] + q2.y * kse_s[2 * m2 + 1];
        }
        gt_s[tid] = gamma[0] / den;
    }
    __syncthreads();

    // preload A fragments: warp covers c slices 32w+16s, s in {0,1}; K=32 -> 2 ksteps
    uint32_t afr[2][2][4];
    #pragma unroll
    for (int s = 0; s < 2; s++) {
        int c0s = 32 * w + 16 * s;
        #pragma unroll
        for (int ks = 0; ks < 2; ks++) {
            const uint32_t* Ap = matTs + (c0s + g) * 20 + 8 * ks + tg;
            afr[s][ks][0] = Ap[0];
            afr[s][ks][1] = Ap[8 * 20];
            afr[s][ks][2] = Ap[4];
            afr[s][ks][3] = Ap[8 * 20 + 4];
        }
    }

    const size_t gbase = (size_t)b * CDIM * NPIX + nb0;

    #pragma unroll 1
    for (int nc = 0; nc < 4; nc++) {
        float acc[2][8][4];
        #pragma unroll
        for (int s = 0; s < 2; s++)
            #pragma unroll
            for (int t = 0; t < 8; t++)
                acc[s][t][0] = acc[s][t][1] = acc[s][t][2] = acc[s][t][3] = 0.f;

        #pragma unroll
        for (int ks = 0; ks < 2; ks++) {
            #pragma unroll
            for (int t = 0; t < 8; t++) {
                int nn = 64 * nc + 8 * t + g;
                uint32_t b0 = Qns[(8 * ks + tg) * 264 + nn];
                uint32_t b1 = Qns[(8 * ks + tg + 4) * 264 + nn];
                mma16816(acc[0][t], afr[0][ks][0], afr[0][ks][1], afr[0][ks][2], afr[0][ks][3], b0, b1);
                mma16816(acc[1][t], afr[1][ks][0], afr[1][ks][1], afr[1][ks][2], afr[1][ks][3], b0, b1);
            }
        }

        // epilogue: out = x + gt*(vs + acc)
        #pragma unroll
        for (int s = 0; s < 2; s++) {
            int c0s = 32 * w + 16 * s;
            float2 xl[8], xh[8];
            #pragma unroll
            for (int t = 0; t < 8; t++) {
                int nn = 64 * nc + 8 * t + 2 * tg;
                xl[t] = *(const float2*)(x + gbase + (size_t)(c0s + g) * NPIX + nn);
                xh[t] = *(const float2*)(x + gbase + (size_t)(c0s + g + 8) * NPIX + nn);
            }
            float v0 = vs_s[c0s + g], v1 = vs_s[c0s + g + 8];
            #pragma unroll
            for (int t = 0; t < 8; t++) {
                int nn = 64 * nc + 8 * t + 2 * tg;
                float gt0 = gt_s[nn], gt1 = gt_s[nn + 1];
                float2 o0, o1;
                o0.x = xl[t].x + gt0 * (v0 + acc[s][t][0]);
                o0.y = xl[t].y + gt1 * (v0 + acc[s][t][1]);
                o1.x = xh[t].x + gt0 * (v1 + acc[s][t][2]);
                o1.y = xh[t].y + gt1 * (v1 + acc[s][t][3]);
                *(float2*)(out + gbase + (size_t)(c0s + g) * NPIX + nn)     = o0;
                *(float2*)(out + gbase + (size_t)(c0s + g + 8) * NPIX + nn) = o1;
            }
        }
    }
}

// ---------------- launch ----------------
extern "C" void kernel_launch(void* const* d_in, const int* in_sizes, int n_in,
                              void* d_out, int out_size)
{
    (void)in_sizes; (void)n_in; (void)out_size;
    const float* x     = (const float*)d_in[0];
    const float* Wq    = (const float*)d_in[1];
    const float* bq    = (const float*)d_in[2];
    const float* Wk    = (const float*)d_in[3];
    const float* bk    = (const float*)d_in[4];
    const float* Wv    = (const float*)d_in[5];
    const float* bv    = (const float*)d_in[6];
    const float* gamma = (const float*)d_in[7];
    float* out = (float*)d_out;

    const int k1_smem = K1_WORDS * (int)sizeof(uint32_t);  // 185216 B
    cudaFuncSetAttribute(k1_kernel, cudaFuncAttributeMaxDynamicSharedMemorySize, k1_smem);

    kinit_kernel<<<64, 256>>>(Wq, Wk);
    k1_kernel<<<dim3(NPIX / TILE_N, BATCH), 256, k1_smem>>>(x, bq, bk);
    k2_kernel<<<dim3(33, BATCH), 256>>>(Wv, bv);
    k3_kernel<<<dim3(NPIX / 256, BATCH), 256>>>(x, gamma, out);
}

// round 13
// speedup vs baseline: 3.0307x; 1.3263x over previous
#include <cuda_runtime.h>
#include <cuda_bf16.h>
#include <cstdint>

#define BATCH 8
#define CDIM 256
#define CQK 32
#define NPIX 16384
#define TILE_N 128
#define NTILES 4

// ---------------- device-global scratch ----------------
__device__ float    g_S[BATCH * CQK * CDIM];       // S = Kn @ X^T (fp32 atomic accum)
__device__ float    g_ksum[BATCH * CQK];
__device__ float    g_xsum[BATCH * CDIM];
__device__ float    g_vs[BATCH * CDIM];
__device__ float    g_kse[BATCH * CQK];
__device__ uint32_t g_Qnh2[BATCH * 16 * NPIX];     // Qn bf162 m-pairs: [b][m2][n]
__device__ uint32_t g_WtT[64 * 128];               // [Wq;Wk] bf162 c-pairs: [r][c2]
__device__ __nv_bfloat16 g_matTh[BATCH * CDIM * CQK]; // matrix^T bf16: [b][c][m]

// ---------------- helpers ----------------
__device__ __forceinline__ uint32_t packbf(float lo, float hi) {
    __nv_bfloat162 h = __float22bfloat162_rn(make_float2(lo, hi));
    return *reinterpret_cast<uint32_t*>(&h);
}

__device__ __forceinline__ void mma16816(float* d,
    uint32_t a0, uint32_t a1, uint32_t a2, uint32_t a3,
    uint32_t b0, uint32_t b1)
{
    asm volatile(
        "mma.sync.aligned.m16n8k16.row.col.f32.bf16.bf16.f32 "
        "{%0,%1,%2,%3}, {%4,%5,%6,%7}, {%8,%9}, {%0,%1,%2,%3};"
        : "+f"(d[0]), "+f"(d[1]), "+f"(d[2]), "+f"(d[3])
        : "r"(a0), "r"(a1), "r"(a2), "r"(a3), "r"(b0), "r"(b1));
}

__device__ __forceinline__ void ldsm4t(uint32_t& a0, uint32_t& a1,
                                       uint32_t& a2, uint32_t& a3, uint32_t addr)
{
    asm volatile("ldmatrix.sync.aligned.m8n8.x4.trans.shared.b16 {%0,%1,%2,%3}, [%4];"
                 : "=r"(a0), "=r"(a1), "=r"(a2), "=r"(a3) : "r"(addr));
}

__device__ __forceinline__ uint32_t smem_u32(const void* p) {
    return (uint32_t)__cvta_generic_to_shared(p);
}

// ---------------- kinit: zero accumulators + build bf16 Wqk [r][c2] ----------------
__global__ void kinit_kernel(const float* __restrict__ Wq, const float* __restrict__ Wk) {
    int i = blockIdx.x * blockDim.x + threadIdx.x;
    int st = gridDim.x * blockDim.x;
    for (int t = i; t < BATCH * CQK * CDIM; t += st) g_S[t] = 0.f;
    for (int t = i; t < BATCH * CQK;  t += st) g_ksum[t] = 0.f;
    for (int t = i; t < BATCH * CDIM; t += st) g_xsum[t] = 0.f;
    for (int t = i; t < 64 * 128; t += st) {
        int r = t >> 7, c2 = t & 127;
        const float* Wr = (r < 32) ? (Wq + r * 256) : (Wk + (r - 32) * 256);
        g_WtT[t] = packbf(Wr[2 * c2], Wr[2 * c2 + 1]);
    }
}

// ---------------- kernel 1: per-block 4 n-tiles; QK mma + normalize + S mma ----------------
// grid (32, 8), 256 threads, dynamic smem 112384 B  -> 2 blocks/SM.
// smem (uint32 words):
//   Xs   [c=256][n2=64] stride 68  (bf16 [c][n])   17408 w
//   WtT  [r=64][c2=128] stride 132                  8448 w
//   Kns  [m=32][n2=64]  stride 68                   2176 w
//   bias [64]
#define K1_XS    0
#define K1_WTT   17408
#define K1_KNS   25856
#define K1_BIAS  28032
#define K1_WORDS 28096

__global__ __launch_bounds__(256, 2) void k1_kernel(
    const float* __restrict__ x,
    const float* __restrict__ bq, const float* __restrict__ bk)
{
    extern __shared__ uint32_t sw[];
    uint32_t* Xs   = sw + K1_XS;
    uint32_t* WtT  = sw + K1_WTT;
    uint32_t* KnsW = sw + K1_KNS;
    float* bias_s  = (float*)(sw + K1_BIAS);
    __nv_bfloat16* KnsH = (__nv_bfloat16*)KnsW;

    const int b    = blockIdx.y;
    const int tid  = threadIdx.x;
    const int w    = tid >> 5;
    const int lane = tid & 31;
    const int g    = lane >> 2;    // 0..7
    const int tg   = lane & 3;     // 0..3

    // stage WtT: g_WtT [r][c2] stride 128 -> smem stride 132 (coalesced, conflict-free)
    #pragma unroll
    for (int i = 0; i < 32; i++) {
        int idx = tid + 256 * i;
        int r = idx >> 7, c2 = idx & 127;
        WtT[r * 132 + c2] = g_WtT[idx];
    }
    if (tid < 64) bias_s[tid] = (tid < 32) ? bq[tid] : bk[tid - 32];

    const float* xb = x + (size_t)b * CDIM * NPIX;
    const int nbase = 16 * w;
    const bool isQ = true; (void)isQ;

    // ldmatrix per-lane source address (halves) within Xs
    const uint32_t lm_base = smem_u32(Xs) +
        (((8 * ((lane >> 4) & 1) + (lane & 7)) * 136 + nbase + (lane & 8)) << 1);

    // persistent accumulators across the 4 tiles
    float sacc[8][4];
    #pragma unroll
    for (int t = 0; t < 8; t++) { sacc[t][0] = sacc[t][1] = sacc[t][2] = sacc[t][3] = 0.f; }
    float xacc = 0.f, kacc = 0.f;

    const int m0 = 16 * (w & 1), c0 = 64 * (w >> 1);   // S-GEMM warp tile
    const int xroff = ((tid >> 3) & 3) << 4;           // xsum phase stagger

    for (int tile = 0; tile < NTILES; tile++) {
        const int n0 = blockIdx.x * (TILE_N * NTILES) + tile * TILE_N;
        __syncthreads();   // previous tile's Xs/Kns consumers done (and staging on iter 0)

        // --- load X tile: warp w owns rows c = 32w..32w+31 ---
        {
            const float* xt = xb + n0;
            #pragma unroll 4
            for (int i = 0; i < 32; i++) {
                int c = 32 * w + i;
                float4 v = *(const float4*)(xt + (size_t)c * NPIX + 4 * lane);
                uint2 rw;
                rw.x = packbf(v.x, v.y); rw.y = packbf(v.z, v.w);
                *(uint2*)(Xs + c * 68 + 2 * lane) = rw;
            }
        }
        __syncthreads();

        // --- xsum partial (row c = tid), 2-phase staggered uint2 reads ---
        {
            const uint32_t* row = Xs + tid * 68;
            #pragma unroll 8
            for (int jj = 0; jj < 32; jj++) {
                int j = (2 * jj + xroff) & 63;
                uint2 u = *(const uint2*)(row + j);
                float2 f0 = __bfloat1622float2(*(const __nv_bfloat162*)&u.x);
                float2 f1 = __bfloat1622float2(*(const __nv_bfloat162*)&u.y);
                xacc += (f0.x + f0.y) + (f1.x + f1.y);
            }
        }

        // --- QK GEMM: out[n][r], M=128(n) N=64(r) K=256(c); A via ldmatrix.trans ---
        float acc[8][4];
        #pragma unroll
        for (int t = 0; t < 8; t++) { acc[t][0] = acc[t][1] = acc[t][2] = acc[t][3] = 0.f; }

        #pragma unroll 4
        for (int ks = 0; ks < 16; ks++) {
            uint32_t a0, a1, a2, a3;
            ldsm4t(a0, a1, a2, a3, lm_base + ks * 4352);
            const uint32_t* Bp = WtT + 8 * ks + tg;
            #pragma unroll
            for (int t = 0; t < 8; t++) {
                const uint32_t* Bt = Bp + (g + 8 * t) * 132;
                mma16816(acc[t], a0, a1, a2, a3, Bt[0], Bt[4]);
            }
        }

        // --- bias + per-pixel channel norms ---
        float qn2a = 0.f, qn2b = 0.f, kn2a = 0.f, kn2b = 0.f;
        #pragma unroll
        for (int t = 0; t < 8; t++) {
            float b0 = bias_s[8 * t + 2 * tg], b1 = bias_s[8 * t + 2 * tg + 1];
            acc[t][0] += b0; acc[t][1] += b1; acc[t][2] += b0; acc[t][3] += b1;
            if (t < 4) {
                qn2a += acc[t][0] * acc[t][0] + acc[t][1] * acc[t][1];
                qn2b += acc[t][2] * acc[t][2] + acc[t][3] * acc[t][3];
            } else {
                kn2a += acc[t][0] * acc[t][0] + acc[t][1] * acc[t][1];
                kn2b += acc[t][2] * acc[t][2] + acc[t][3] * acc[t][3];
            }
        }
        qn2a += __shfl_xor_sync(0xffffffffu, qn2a, 1); qn2a += __shfl_xor_sync(0xffffffffu, qn2a, 2);
        qn2b += __shfl_xor_sync(0xffffffffu, qn2b, 1); qn2b += __shfl_xor_sync(0xffffffffu, qn2b, 2);
        kn2a += __shfl_xor_sync(0xffffffffu, kn2a, 1); kn2a += __shfl_xor_sync(0xffffffffu, kn2a, 2);
        kn2b += __shfl_xor_sync(0xffffffffu, kn2b, 1); kn2b += __shfl_xor_sync(0xffffffffu, kn2b, 2);
        const float rqa = rsqrtf(qn2a), rqb = rsqrtf(qn2b);
        const float rka = rsqrtf(kn2a), rkb = rsqrtf(kn2b);

        // --- Qn -> global bf162 m-pairs ---
        {
            uint32_t* qdst = g_Qnh2 + (size_t)b * 16 * NPIX + n0 + nbase + g;
            #pragma unroll
            for (int t = 0; t < 4; t++) {
                int r2 = 4 * t + tg;
                qdst[(size_t)r2 * NPIX]     = packbf(acc[t][0] * rqa, acc[t][1] * rqa);
                qdst[(size_t)r2 * NPIX + 8] = packbf(acc[t][2] * rqb, acc[t][3] * rqb);
            }
        }

        // --- Kn -> smem bf16 [m][n] ---
        #pragma unroll
        for (int t = 4; t < 8; t++) {
            int m = 8 * (t - 4) + 2 * tg;
            int nn = nbase + g;
            KnsH[m * 136 + nn]           = __float2bfloat16(acc[t][0] * rka);
            KnsH[(m + 1) * 136 + nn]     = __float2bfloat16(acc[t][1] * rka);
            KnsH[m * 136 + nn + 8]       = __float2bfloat16(acc[t][2] * rkb);
            KnsH[(m + 1) * 136 + nn + 8] = __float2bfloat16(acc[t][3] * rkb);
        }
        __syncthreads();

        // --- ksum partial: 8 threads per m-row ---
        {
            int m = tid >> 3;
            const uint32_t* row = KnsW + m * 68 + ((tid & 7) << 3);
            #pragma unroll
            for (int jj = 0; jj < 4; jj++) {
                uint2 u = *(const uint2*)(row + 2 * jj);
                float2 f0 = __bfloat1622float2(*(const __nv_bfloat162*)&u.x);
                float2 f1 = __bfloat1622float2(*(const __nv_bfloat162*)&u.y);
                kacc += (f0.x + f0.y) + (f1.x + f1.y);
            }
        }

        // --- S GEMM: S[m][c] += Kn @ X^T; M=32 N=256 K=128 ---
        #pragma unroll
        for (int ks = 0; ks < 8; ks++) {
            const uint32_t* Ap = KnsW + (m0 + g) * 68 + 8 * ks + tg;
            uint32_t a0 = Ap[0], a1 = Ap[8 * 68], a2 = Ap[4], a3 = Ap[8 * 68 + 4];
            const uint32_t* Bp = Xs + (c0 + g) * 68 + 8 * ks + tg;
            #pragma unroll
            for (int t = 0; t < 8; t++)
                mma16816(sacc[t], a0, a1, a2, a3, Bp[8 * t * 68], Bp[8 * t * 68 + 4]);
        }
    }

    // --- flush accumulators ---
    float* Sb = g_S + (size_t)b * CQK * CDIM;
    #pragma unroll
    for (int t = 0; t < 8; t++) {
        int c = c0 + 8 * t + 2 * tg;
        atomicAdd(&Sb[(m0 + g) * CDIM + c],         sacc[t][0]);
        atomicAdd(&Sb[(m0 + g) * CDIM + c + 1],     sacc[t][1]);
        atomicAdd(&Sb[(m0 + g + 8) * CDIM + c],     sacc[t][2]);
        atomicAdd(&Sb[(m0 + g + 8) * CDIM + c + 1], sacc[t][3]);
    }
    atomicAdd(&g_xsum[b * CDIM + tid], xacc);
    kacc += __shfl_xor_sync(0xffffffffu, kacc, 1);
    kacc += __shfl_xor_sync(0xffffffffu, kacc, 2);
    kacc += __shfl_xor_sync(0xffffffffu, kacc, 4);
    if ((tid & 7) == 0) atomicAdd(&g_ksum[b * CQK + (tid >> 3)], kacc);
}

// ---------------- kernel 2: matrix^T (bf16) = (S @ Wv^T + ksum x bv)^T ; value_sum ----------------
__global__ __launch_bounds__(256) void k2_kernel(
    const float* __restrict__ Wv, const float* __restrict__ bv)
{
    __shared__ float Wvs[256 * 33];
    __shared__ float Ss[256];
    const int b   = blockIdx.y;
    const int m   = blockIdx.x;
    const int tid = threadIdx.x;

    const float* srow = (m < 32) ? (g_S + (b * CQK + m) * CDIM) : (g_xsum + b * CDIM);
    Ss[tid] = srow[tid];

    float acc = 0.f;
    for (int k0 = 0; k0 < 256; k0 += 32) {
        #pragma unroll
        for (int i = 0; i < 8; i++) {
            int f4 = tid + 256 * i;
            int r  = f4 >> 3;
            int k4 = (f4 & 7) << 2;
            float4 wv = *(const float4*)(Wv + r * 256 + k0 + k4);
            float* d = Wvs + r * 33 + k4;
            d[0] = wv.x; d[1] = wv.y; d[2] = wv.z; d[3] = wv.w;
        }
        __syncthreads();
        #pragma unroll
        for (int kk = 0; kk < 32; kk++)
            acc = fmaf(Wvs[tid * 33 + kk], Ss[k0 + kk], acc);
        __syncthreads();
    }

    if (m < 32) {
        float bm = g_ksum[b * CQK + m];
        g_matTh[((size_t)b * CDIM + tid) * CQK + m] = __float2bfloat16(acc + bv[tid] * bm);
    } else {
        g_vs[b * CDIM + tid] = acc + 16384.0f * bv[tid];
        if (tid < 32) g_kse[b * CQK + tid] = g_ksum[b * CQK + tid] + 1e-6f;
    }
}

// ---------------- kernel 3 (mma): out = x + gt * (vs + matrix^T @ Qn) ----------------
// grid (64, 8), 256 threads, 3 blocks/SM. Tile: 256 channels x 256 pixels.
__global__ __launch_bounds__(256, 3) void k3_kernel(
    const float* __restrict__ x, const float* __restrict__ gamma,
    float* __restrict__ out)
{
    __shared__ uint32_t matTs[256 * 20];   // A: [c][m2] stride 20
    __shared__ uint32_t Qns[16 * 264];     // B: [m2][n] stride 264
    __shared__ float gt_s[256];
    __shared__ float vs_s[256];
    __shared__ float kse_s[32];

    const int b    = blockIdx.y;
    const int nb0  = blockIdx.x * 256;
    const int tid  = threadIdx.x;
    const int w    = tid >> 5;
    const int lane = tid & 31;
    const int g    = lane >> 2;
    const int tg   = lane & 3;

    // stage matrix^T (bf162 m-pairs) and Qn tile
    {
        const uint32_t* mt = (const uint32_t*)g_matTh + ((size_t)b * CDIM + tid) * 16;
        uint32_t* dst = matTs + tid * 20;
        #pragma unroll
        for (int j = 0; j < 16; j += 4) *(uint4*)(dst + j) = *(const uint4*)(mt + j);
    }
    #pragma unroll
    for (int i = 0; i < 16; i++)
        Qns[i * 264 + tid] = g_Qnh2[((size_t)b * 16 + i) * NPIX + nb0 + tid];
    vs_s[tid] = g_vs[b * CDIM + tid];
    if (tid < 32) kse_s[tid] = g_kse[b * CQK + tid];
    __syncthreads();

    // gt[n] = gamma / (N + sum_m q[m]*kse[m])
    {
        float den = 16384.0f;
        #pragma unroll
        for (int m2 = 0; m2 < 16; m2++) {
            float2 q2 = __bfloat1622float2(*(const __nv_bfloat162*)&Qns[m2 * 264 + tid]);
            den += q2.x * kse_s[2 * m2] + q2.y * kse_s[2 * m2 + 1];
        }
        gt_s[tid] = gamma[0] / den;
    }
    __syncthreads();

    const size_t gbase = (size_t)b * CDIM * NPIX + nb0;

    #pragma unroll 1
    for (int s = 0; s < 2; s++) {
        const int c0s = 32 * w + 16 * s;
        uint32_t afr[2][4];
        #pragma unroll
        for (int ks = 0; ks < 2; ks++) {
            const uint32_t* Ap = matTs + (c0s + g) * 20 + 8 * ks + tg;
            afr[ks][0] = Ap[0];
            afr[ks][1] = Ap[8 * 20];
            afr[ks][2] = Ap[4];
            afr[ks][3] = Ap[8 * 20 + 4];
        }
        const float v0 = vs_s[c0s + g], v1 = vs_s[c0s + g + 8];
        const float* xr0 = x   + gbase + (size_t)(c0s + g) * NPIX;
        const float* xr1 = x   + gbase + (size_t)(c0s + g + 8) * NPIX;
        float*       or0 = out + gbase + (size_t)(c0s + g) * NPIX;
        float*       or1 = out + gbase + (size_t)(c0s + g + 8) * NPIX;

        #pragma unroll 1
        for (int nc = 0; nc < 4; nc++) {
            float acc[8][4];
            #pragma unroll
            for (int t = 0; t < 8; t++)
                acc[t][0] = acc[t][1] = acc[t][2] = acc[t][3] = 0.f;

            #pragma unroll
            for (int ks = 0; ks < 2; ks++) {
                #pragma unroll
                for (int t = 0; t < 8; t++) {
                    int nn = 64 * nc + 8 * t + g;
                    uint32_t b0 = Qns[(8 * ks + tg) * 264 + nn];
                    uint32_t b1 = Qns[(8 * ks + tg + 4) * 264 + nn];
                    mma16816(acc[t], afr[ks][0], afr[ks][1], afr[ks][2], afr[ks][3], b0, b1);
                }
            }

            // epilogue in two half-batches (8 loads in flight each)
            #pragma unroll
            for (int h = 0; h < 2; h++) {
                float2 xl[4], xh[4];
                #pragma unroll
                for (int t4 = 0; t4 < 4; t4++) {
                    int nn2 = 64 * nc + 8 * (4 * h + t4) + 2 * tg;
                    xl[t4] = *(const float2*)(xr0 + nn2);
                    xh[t4] = *(const float2*)(xr1 + nn2);
                }
                #pragma unroll
                for (int t4 = 0; t4 < 4; t4++) {
                    int t = 4 * h + t4;
                    int nn2 = 64 * nc + 8 * t + 2 * tg;
                    float gt0 = gt_s[nn2], gt1 = gt_s[nn2 + 1];
                    float2 o0, o1;
                    o0.x = xl[t4].x + gt0 * (v0 + acc[t][0]);
                    o0.y = xl[t4].y + gt1 * (v0 + acc[t][1]);
                    o1.x = xh[t4].x + gt0 * (v1 + acc[t][2]);
                    o1.y = xh[t4].y + gt1 * (v1 + acc[t][3]);
                    *(float2*)(or0 + nn2) = o0;
                    *(float2*)(or1 + nn2) = o1;
                }
            }
        }
    }
}

// ---------------- launch ----------------
extern "C" void kernel_launch(void* const* d_in, const int* in_sizes, int n_in,
                              void* d_out, int out_size)
{
    (void)in_sizes; (void)n_in; (void)out_size;
    const float* x     = (const float*)d_in[0];
    const float* Wq    = (const float*)d_in[1];
    const float* bq    = (const float*)d_in[2];
    const float* Wk    = (const float*)d_in[3];
    const float* bk    = (const float*)d_in[4];
    const float* Wv    = (const float*)d_in[5];
    const float* bv    = (const float*)d_in[6];
    const float* gamma = (const float*)d_in[7];
    float* out = (float*)d_out;

    const int k1_smem = K1_WORDS * (int)sizeof(uint32_t);  // 112384 B -> 2 blocks/SM
    cudaFuncSetAttribute(k1_kernel, cudaFuncAttributeMaxDynamicSharedMemorySize, k1_smem);

    kinit_kernel<<<64, 256>>>(Wq, Wk);
    k1_kernel<<<dim3(NPIX / (TILE_N * NTILES), BATCH), 256, k1_smem>>>(x, bq, bk);
    k2_kernel<<<dim3(33, BATCH), 256>>>(Wv, bv);
    k3_kernel<<<dim3(NPIX / 256, BATCH), 256>>>(x, gamma, out);
}

// round 14
// speedup vs baseline: 3.0345x; 1.0013x over previous
#include <cuda_runtime.h>
#include <cuda_bf16.h>
#include <cstdint>

#define BATCH 8
#define CDIM 256
#define CQK 32
#define NPIX 16384
#define TILE_N 128
#define NTILES 2

// ---------------- device-global scratch ----------------
__device__ float    g_S[BATCH * CQK * CDIM];       // S = Kn @ X^T (fp32 atomic accum)
__device__ float    g_ksum[BATCH * CQK];
__device__ float    g_xsum[BATCH * CDIM];
__device__ float    g_vs[BATCH * CDIM];
__device__ float    g_kse[BATCH * CQK];
__device__ uint32_t g_Qnh2[BATCH * 16 * NPIX];     // Qn bf162 m-pairs: [b][m2][n]
__device__ uint32_t g_WtT[64 * 128];               // [Wq;Wk] bf162 c-pairs: [r][c2]
__device__ __nv_bfloat16 g_matTh[BATCH * CDIM * CQK]; // matrix^T bf16: [b][c][m]

// ---------------- helpers ----------------
__device__ __forceinline__ uint32_t packbf(float lo, float hi) {
    __nv_bfloat162 h = __float22bfloat162_rn(make_float2(lo, hi));
    return *reinterpret_cast<uint32_t*>(&h);
}

__device__ __forceinline__ void mma16816(float* d,
    uint32_t a0, uint32_t a1, uint32_t a2, uint32_t a3,
    uint32_t b0, uint32_t b1)
{
    asm volatile(
        "mma.sync.aligned.m16n8k16.row.col.f32.bf16.bf16.f32 "
        "{%0,%1,%2,%3}, {%4,%5,%6,%7}, {%8,%9}, {%0,%1,%2,%3};"
        : "+f"(d[0]), "+f"(d[1]), "+f"(d[2]), "+f"(d[3])
        : "r"(a0), "r"(a1), "r"(a2), "r"(a3), "r"(b0), "r"(b1));
}

__device__ __forceinline__ void ldsm4t(uint32_t& a0, uint32_t& a1,
                                       uint32_t& a2, uint32_t& a3, uint32_t addr)
{
    asm volatile("ldmatrix.sync.aligned.m8n8.x4.trans.shared.b16 {%0,%1,%2,%3}, [%4];"
                 : "=r"(a0), "=r"(a1), "=r"(a2), "=r"(a3) : "r"(addr));
}

__device__ __forceinline__ uint32_t smem_u32(const void* p) {
    return (uint32_t)__cvta_generic_to_shared(p);
}

// ---------------- kinit: zero accumulators + build bf16 Wqk [r][c2] ----------------
__global__ void kinit_kernel(const float* __restrict__ Wq, const float* __restrict__ Wk) {
    int i = blockIdx.x * blockDim.x + threadIdx.x;
    int st = gridDim.x * blockDim.x;
    for (int t = i; t < BATCH * CQK * CDIM; t += st) g_S[t] = 0.f;
    for (int t = i; t < BATCH * CQK;  t += st) g_ksum[t] = 0.f;
    for (int t = i; t < BATCH * CDIM; t += st) g_xsum[t] = 0.f;
    for (int t = i; t < 64 * 128; t += st) {
        int r = t >> 7, c2 = t & 127;
        const float* Wr = (r < 32) ? (Wq + r * 256) : (Wk + (r - 32) * 256);
        g_WtT[t] = packbf(Wr[2 * c2], Wr[2 * c2 + 1]);
    }
}

// ---------------- kernel 1: per-block NTILES n-tiles; QK mma + normalize + S mma ----------------
// grid (64, 8), 256 threads, dynamic smem 112384 B  -> 2 blocks/SM.
#define K1_XS    0
#define K1_WTT   17408
#define K1_KNS   25856
#define K1_BIAS  28032
#define K1_WORDS 28096

__global__ __launch_bounds__(256, 2) void k1_kernel(
    const float* __restrict__ x,
    const float* __restrict__ bq, const float* __restrict__ bk)
{
    extern __shared__ uint32_t sw[];
    uint32_t* Xs   = sw + K1_XS;
    uint32_t* WtT  = sw + K1_WTT;
    uint32_t* KnsW = sw + K1_KNS;
    float* bias_s  = (float*)(sw + K1_BIAS);
    __nv_bfloat16* KnsH = (__nv_bfloat16*)KnsW;

    const int b    = blockIdx.y;
    const int tid  = threadIdx.x;
    const int w    = tid >> 5;
    const int lane = tid & 31;
    const int g    = lane >> 2;    // 0..7
    const int tg   = lane & 3;     // 0..3

    // stage WtT: g_WtT [r][c2] stride 128 -> smem stride 132
    #pragma unroll
    for (int i = 0; i < 32; i++) {
        int idx = tid + 256 * i;
        int r = idx >> 7, c2 = idx & 127;
        WtT[r * 132 + c2] = g_WtT[idx];
    }
    if (tid < 64) bias_s[tid] = (tid < 32) ? bq[tid] : bk[tid - 32];

    const float* xb = x + (size_t)b * CDIM * NPIX;
    const int nbase = 16 * w;

    const uint32_t lm_base = smem_u32(Xs) +
        (((8 * ((lane >> 4) & 1) + (lane & 7)) * 136 + nbase + (lane & 8)) << 1);

    float sacc[8][4];
    #pragma unroll
    for (int t = 0; t < 8; t++) { sacc[t][0] = sacc[t][1] = sacc[t][2] = sacc[t][3] = 0.f; }
    float xacc = 0.f, kacc = 0.f;

    const int m0 = 16 * (w & 1), c0 = 64 * (w >> 1);
    const int xroff = ((tid >> 3) & 3) << 4;

    for (int tile = 0; tile < NTILES; tile++) {
        const int n0 = blockIdx.x * (TILE_N * NTILES) + tile * TILE_N;
        __syncthreads();

        // --- load X tile: warp w owns rows c = 32w..32w+31 ---
        {
            const float* xt = xb + n0;
            #pragma unroll 4
            for (int i = 0; i < 32; i++) {
                int c = 32 * w + i;
                float4 v = *(const float4*)(xt + (size_t)c * NPIX + 4 * lane);
                uint2 rw;
                rw.x = packbf(v.x, v.y); rw.y = packbf(v.z, v.w);
                *(uint2*)(Xs + c * 68 + 2 * lane) = rw;
            }
        }
        __syncthreads();

        // --- xsum partial ---
        {
            const uint32_t* row = Xs + tid * 68;
            #pragma unroll 8
            for (int jj = 0; jj < 32; jj++) {
                int j = (2 * jj + xroff) & 63;
                uint2 u = *(const uint2*)(row + j);
                float2 f0 = __bfloat1622float2(*(const __nv_bfloat162*)&u.x);
                float2 f1 = __bfloat1622float2(*(const __nv_bfloat162*)&u.y);
                xacc += (f0.x + f0.y) + (f1.x + f1.y);
            }
        }

        // --- QK GEMM ---
        float acc[8][4];
        #pragma unroll
        for (int t = 0; t < 8; t++) { acc[t][0] = acc[t][1] = acc[t][2] = acc[t][3] = 0.f; }

        #pragma unroll 4
        for (int ks = 0; ks < 16; ks++) {
            uint32_t a0, a1, a2, a3;
            ldsm4t(a0, a1, a2, a3, lm_base + ks * 4352);
            const uint32_t* Bp = WtT + 8 * ks + tg;
            #pragma unroll
            for (int t = 0; t < 8; t++) {
                const uint32_t* Bt = Bp + (g + 8 * t) * 132;
                mma16816(acc[t], a0, a1, a2, a3, Bt[0], Bt[4]);
            }
        }

        // --- bias + norms ---
        float qn2a = 0.f, qn2b = 0.f, kn2a = 0.f, kn2b = 0.f;
        #pragma unroll
        for (int t = 0; t < 8; t++) {
            float b0 = bias_s[8 * t + 2 * tg], b1 = bias_s[8 * t + 2 * tg + 1];
            acc[t][0] += b0; acc[t][1] += b1; acc[t][2] += b0; acc[t][3] += b1;
            if (t < 4) {
                qn2a += acc[t][0] * acc[t][0] + acc[t][1] * acc[t][1];
                qn2b += acc[t][2] * acc[t][2] + acc[t][3] * acc[t][3];
            } else {
                kn2a += acc[t][0] * acc[t][0] + acc[t][1] * acc[t][1];
                kn2b += acc[t][2] * acc[t][2] + acc[t][3] * acc[t][3];
            }
        }
        qn2a += __shfl_xor_sync(0xffffffffu, qn2a, 1); qn2a += __shfl_xor_sync(0xffffffffu, qn2a, 2);
        qn2b += __shfl_xor_sync(0xffffffffu, qn2b, 1); qn2b += __shfl_xor_sync(0xffffffffu, qn2b, 2);
        kn2a += __shfl_xor_sync(0xffffffffu, kn2a, 1); kn2a += __shfl_xor_sync(0xffffffffu, kn2a, 2);
        kn2b += __shfl_xor_sync(0xffffffffu, kn2b, 1); kn2b += __shfl_xor_sync(0xffffffffu, kn2b, 2);
        const float rqa = rsqrtf(qn2a), rqb = rsqrtf(qn2b);
        const float rka = rsqrtf(kn2a), rkb = rsqrtf(kn2b);

        // --- Qn -> global ---
        {
            uint32_t* qdst = g_Qnh2 + (size_t)b * 16 * NPIX + n0 + nbase + g;
            #pragma unroll
            for (int t = 0; t < 4; t++) {
                int r2 = 4 * t + tg;
                qdst[(size_t)r2 * NPIX]     = packbf(acc[t][0] * rqa, acc[t][1] * rqa);
                qdst[(size_t)r2 * NPIX + 8] = packbf(acc[t][2] * rqb, acc[t][3] * rqb);
            }
        }

        // --- Kn -> smem ---
        #pragma unroll
        for (int t = 4; t < 8; t++) {
            int m = 8 * (t - 4) + 2 * tg;
            int nn = nbase + g;
            KnsH[m * 136 + nn]           = __float2bfloat16(acc[t][0] * rka);
            KnsH[(m + 1) * 136 + nn]     = __float2bfloat16(acc[t][1] * rka);
            KnsH[m * 136 + nn + 8]       = __float2bfloat16(acc[t][2] * rkb);
            KnsH[(m + 1) * 136 + nn + 8] = __float2bfloat16(acc[t][3] * rkb);
        }
        __syncthreads();

        // --- ksum partial ---
        {
            int m = tid >> 3;
            const uint32_t* row = KnsW + m * 68 + ((tid & 7) << 3);
            #pragma unroll
            for (int jj = 0; jj < 4; jj++) {
                uint2 u = *(const uint2*)(row + 2 * jj);
                float2 f0 = __bfloat1622float2(*(const __nv_bfloat162*)&u.x);
                float2 f1 = __bfloat1622float2(*(const __nv_bfloat162*)&u.y);
                kacc += (f0.x + f0.y) + (f1.x + f1.y);
            }
        }

        // --- S GEMM ---
        #pragma unroll
        for (int ks = 0; ks < 8; ks++) {
            const uint32_t* Ap = KnsW + (m0 + g) * 68 + 8 * ks + tg;
            uint32_t a0 = Ap[0], a1 = Ap[8 * 68], a2 = Ap[4], a3 = Ap[8 * 68 + 4];
            const uint32_t* Bp = Xs + (c0 + g) * 68 + 8 * ks + tg;
            #pragma unroll
            for (int t = 0; t < 8; t++)
                mma16816(sacc[t], a0, a1, a2, a3, Bp[8 * t * 68], Bp[8 * t * 68 + 4]);
        }
    }

    // --- flush ---
    float* Sb = g_S + (size_t)b * CQK * CDIM;
    #pragma unroll
    for (int t = 0; t < 8; t++) {
        int c = c0 + 8 * t + 2 * tg;
        atomicAdd(&Sb[(m0 + g) * CDIM + c],         sacc[t][0]);
        atomicAdd(&Sb[(m0 + g) * CDIM + c + 1],     sacc[t][1]);
        atomicAdd(&Sb[(m0 + g + 8) * CDIM + c],     sacc[t][2]);
        atomicAdd(&Sb[(m0 + g + 8) * CDIM + c + 1], sacc[t][3]);
    }
    atomicAdd(&g_xsum[b * CDIM + tid], xacc);
    kacc += __shfl_xor_sync(0xffffffffu, kacc, 1);
    kacc += __shfl_xor_sync(0xffffffffu, kacc, 2);
    kacc += __shfl_xor_sync(0xffffffffu, kacc, 4);
    if ((tid & 7) == 0) atomicAdd(&g_ksum[b * CQK + (tid >> 3)], kacc);
}

// ---------------- kernel 2: matrix^T/vs per (c-chunk, batch) block ----------------
// grid (8, 8), 256 threads, dynamic smem ~68 KB.
// smem (floats): Wvt [k=256][c=33 pad] 8448 ; Ss [m=32][k stride 260] 8320 ;
//                xsum[256] ; bv[32] ; ksum[32]
#define K2_WVT   0
#define K2_SS    8448
#define K2_XSUM  16768
#define K2_BV    17024
#define K2_KSUM  17056
#define K2_FLOATS 17088

__global__ __launch_bounds__(256, 2) void k2_kernel(
    const float* __restrict__ Wv, const float* __restrict__ bv)
{
    extern __shared__ float sf[];
    float* Wvt    = sf + K2_WVT;   // [k][c_l] stride 33
    float* Ss     = sf + K2_SS;    // [m][k]  stride 260
    float* xsum_s = sf + K2_XSUM;
    float* bv_s   = sf + K2_BV;
    float* ksum_s = sf + K2_KSUM;

    const int b   = blockIdx.y;
    const int c0  = blockIdx.x * 32;
    const int tid = threadIdx.x;

    // stage Wv chunk transposed: rows c0..c0+31
    {
        int r = tid >> 3, seg = (tid & 7) * 32;
        const float* src = Wv + (c0 + r) * 256 + seg;
        #pragma unroll
        for (int j4 = 0; j4 < 32; j4 += 4) {
            float4 v = *(const float4*)(src + j4);
            Wvt[(seg + j4) * 33 + r]     = v.x;
            Wvt[(seg + j4 + 1) * 33 + r] = v.y;
            Wvt[(seg + j4 + 2) * 33 + r] = v.z;
            Wvt[(seg + j4 + 3) * 33 + r] = v.w;
        }
    }
    // stage S_b [32][256]
    {
        const float* Sb = g_S + (size_t)b * CQK * CDIM;
        #pragma unroll
        for (int i = 0; i < 8; i++) {
            int idx4 = tid + 256 * i;
            int m = idx4 >> 6, col = (idx4 & 63) << 2;
            *(float4*)(Ss + m * 260 + col) = *(const float4*)(Sb + m * 256 + col);
        }
    }
    xsum_s[tid] = g_xsum[b * CDIM + tid];
    if (tid < 32) { bv_s[tid] = bv[c0 + tid]; ksum_s[tid] = g_ksum[b * CQK + tid]; }
    __syncthreads();

    const int c_l = tid & 31;
    const int mg  = tid >> 5;     // 0..7 -> m = 4*mg..4*mg+3
    float acc0 = 0.f, acc1 = 0.f, acc2 = 0.f, acc3 = 0.f, accv = 0.f;
    const float* S0 = Ss + (4 * mg) * 260;
    #pragma unroll 8
    for (int k = 0; k < 256; k++) {
        float wv = Wvt[k * 33 + c_l];
        acc0 = fmaf(wv, S0[k],            acc0);
        acc1 = fmaf(wv, S0[260 + k],      acc1);
        acc2 = fmaf(wv, S0[2 * 260 + k],  acc2);
        acc3 = fmaf(wv, S0[3 * 260 + k],  acc3);
        accv = fmaf(wv, xsum_s[k],        accv);
    }

    const int c = c0 + c_l;
    const float bvc = bv_s[c_l];
    __nv_bfloat16* mdst = g_matTh + ((size_t)b * CDIM + c) * CQK + 4 * mg;
    mdst[0] = __float2bfloat16(acc0 + bvc * ksum_s[4 * mg]);
    mdst[1] = __float2bfloat16(acc1 + bvc * ksum_s[4 * mg + 1]);
    mdst[2] = __float2bfloat16(acc2 + bvc * ksum_s[4 * mg + 2]);
    mdst[3] = __float2bfloat16(acc3 + bvc * ksum_s[4 * mg + 3]);
    if (mg == 0) g_vs[b * CDIM + c] = accv + 16384.0f * bvc;
    if (blockIdx.x == 0 && tid < 32) g_kse[b * CQK + tid] = ksum_s[tid] + 1e-6f;
}

// ---------------- kernel 3 (mma): out = x + gt * (vs + matrix^T @ Qn) ----------------
// grid (64 n-tiles, 2 c-halves, 8 batch), 256 threads, 3 blocks/SM.
// Block tile: 128 channels x 256 pixels; x loads prefetched ahead of mma.
__global__ __launch_bounds__(256, 3) void k3_kernel(
    const float* __restrict__ x, const float* __restrict__ gamma,
    float* __restrict__ out)
{
    __shared__ uint32_t matTs[128 * 20];   // A: [c_l][m2] stride 20
    __shared__ uint32_t Qns[16 * 264];     // B: [m2][n] stride 264
    __shared__ float gt_s[256];
    __shared__ float vs_s[128];
    __shared__ float kse_s[32];

    const int b     = blockIdx.z;
    const int c0blk = blockIdx.y * 128;
    const int nb0   = blockIdx.x * 256;
    const int tid   = threadIdx.x;
    const int w     = tid >> 5;
    const int lane  = tid & 31;
    const int g     = lane >> 2;
    const int tg    = lane & 3;

    // stage matrix^T (bf162 m-pairs) for this c-half
    {
        int row = tid >> 1, half = (tid & 1) * 8;
        const uint32_t* mt = (const uint32_t*)g_matTh + ((size_t)b * CDIM + c0blk + row) * 16 + half;
        uint32_t* dst = matTs + row * 20 + half;
        *(uint4*)(dst)     = *(const uint4*)(mt);
        *(uint4*)(dst + 4) = *(const uint4*)(mt + 4);
    }
    #pragma unroll
    for (int i = 0; i < 16; i++)
        Qns[i * 264 + tid] = g_Qnh2[((size_t)b * 16 + i) * NPIX + nb0 + tid];
    if (tid < 128) vs_s[tid] = g_vs[b * CDIM + c0blk + tid];
    if (tid < 32)  kse_s[tid] = g_kse[b * CQK + tid];
    __syncthreads();

    // gt[n] = gamma / (N + sum_m q[m]*kse[m])
    {
        float den = 16384.0f;
        #pragma unroll
        for (int m2 = 0; m2 < 16; m2++) {
            float2 q2 = __bfloat1622float2(*(const __nv_bfloat162*)&Qns[m2 * 264 + tid]);
            den += q2.x * kse_s[2 * m2] + q2.y * kse_s[2 * m2 + 1];
        }
        gt_s[tid] = gamma[0] / den;
    }
    __syncthreads();

    const int c_l0 = 16 * w;
    uint32_t afr[2][4];
    #pragma unroll
    for (int ks = 0; ks < 2; ks++) {
        const uint32_t* Ap = matTs + (c_l0 + g) * 20 + 8 * ks + tg;
        afr[ks][0] = Ap[0];
        afr[ks][1] = Ap[8 * 20];
        afr[ks][2] = Ap[4];
        afr[ks][3] = Ap[8 * 20 + 4];
    }
    const float v0 = vs_s[c_l0 + g], v1 = vs_s[c_l0 + g + 8];
    const size_t rbase = (size_t)b * CDIM * NPIX + (size_t)(c0blk + c_l0 + g) * NPIX + nb0;
    const float* xr0 = x + rbase;
    const float* xr1 = x + rbase + (size_t)8 * NPIX;
    float*       or0 = out + rbase;
    float*       or1 = out + rbase + (size_t)8 * NPIX;

    #pragma unroll 1
    for (int nc = 0; nc < 4; nc++) {
        // prefetch all x for this chunk (16 loads in flight across the mma)
        float2 xl[8], xh[8];
        #pragma unroll
        for (int t = 0; t < 8; t++) {
            int nn2 = 64 * nc + 8 * t + 2 * tg;
            xl[t] = *(const float2*)(xr0 + nn2);
            xh[t] = *(const float2*)(xr1 + nn2);
        }

        float acc[8][4];
        #pragma unroll
        for (int t = 0; t < 8; t++)
            acc[t][0] = acc[t][1] = acc[t][2] = acc[t][3] = 0.f;

        #pragma unroll
        for (int ks = 0; ks < 2; ks++) {
            #pragma unroll
            for (int t = 0; t < 8; t++) {
                int nn = 64 * nc + 8 * t + g;
                uint32_t b0 = Qns[(8 * ks + tg) * 264 + nn];
                uint32_t b1 = Qns[(8 * ks + tg + 4) * 264 + nn];
                mma16816(acc[t], afr[ks][0], afr[ks][1], afr[ks][2], afr[ks][3], b0, b1);
            }
        }

        #pragma unroll
        for (int t = 0; t < 8; t++) {
            int nn2 = 64 * nc + 8 * t + 2 * tg;
            float gt0 = gt_s[nn2], gt1 = gt_s[nn2 + 1];
            float2 o0, o1;
            o0.x = xl[t].x + gt0 * (v0 + acc[t][0]);
            o0.y = xl[t].y + gt1 * (v0 + acc[t][1]);
            o1.x = xh[t].x + gt0 * (v1 + acc[t][2]);
            o1.y = xh[t].y + gt1 * (v1 + acc[t][3]);
            *(float2*)(or0 + nn2) = o0;
            *(float2*)(or1 + nn2) = o1;
        }
    }
}

// ---------------- launch ----------------
extern "C" void kernel_launch(void* const* d_in, const int* in_sizes, int n_in,
                              void* d_out, int out_size)
{
    (void)in_sizes; (void)n_in; (void)out_size;
    const float* x     = (const float*)d_in[0];
    const float* Wq    = (const float*)d_in[1];
    const float* bq    = (const float*)d_in[2];
    const float* Wk    = (const float*)d_in[3];
    const float* bk    = (const float*)d_in[4];
    const float* Wv    = (const float*)d_in[5];
    const float* bv    = (const float*)d_in[6];
    const float* gamma = (const float*)d_in[7];
    float* out = (float*)d_out;

    const int k1_smem = K1_WORDS * (int)sizeof(uint32_t);  // 112384 B -> 2 blocks/SM
    cudaFuncSetAttribute(k1_kernel, cudaFuncAttributeMaxDynamicSharedMemorySize, k1_smem);
    const int k2_smem = K2_FLOATS * (int)sizeof(float);    // 68352 B
    cudaFuncSetAttribute(k2_kernel, cudaFuncAttributeMaxDynamicSharedMemorySize, k2_smem);

    kinit_kernel<<<132, 256>>>(Wq, Wk);
    k1_kernel<<<dim3(NPIX / (TILE_N * NTILES), BATCH), 256, k1_smem>>>(x, bq, bk);
    k2_kernel<<<dim3(8, BATCH), 256, k2_smem>>>(Wv, bv);
    k3_kernel<<<dim3(NPIX / 256, 2, BATCH), 256>>>(x, gamma, out);
}